// round 1
// baseline (speedup 1.0000x reference)
#include <cuda_runtime.h>
#include <cuda_bf16.h>

// CBOW hierarchical-softmax loss.
// Inputs (metadata order):
//   d_in[0] context_idxs  int32 [B, C]   B=65536, C=10
//   d_in[1] path_nodes    int32 [B, D]   D=18
//   d_in[2] codes         int32 [B, D]
//   d_in[3] in_embed      f32   [V, E]   V=100000, E=128
//   d_in[4] node_embed    f32   [N, E]   N=99999
// Output: loss f32 [B]
//
// One warp per example. Each lane owns 4 columns (float4) of the E=128 row.

#define B_ 65536
#define C_ 10
#define D_ 18
#define E_ 128
#define EPS_ 1e-9f

__global__ void __launch_bounds__(256) cbow_hs_kernel(
    const int* __restrict__ ctx,
    const int* __restrict__ path,
    const int* __restrict__ codes,
    const float* __restrict__ in_emb,
    const float* __restrict__ node_emb,
    float* __restrict__ out)
{
    const int warp = (blockIdx.x * blockDim.x + threadIdx.x) >> 5;
    const int lane = threadIdx.x & 31;
    if (warp >= B_) return;

    const float4* __restrict__ in4 = reinterpret_cast<const float4*>(in_emb);
    const float4* __restrict__ nd4 = reinterpret_cast<const float4*>(node_emb);

    // ---- context mean: v ----
    int cidx[C_];
#pragma unroll
    for (int j = 0; j < C_; j++)
        cidx[j] = __ldg(&ctx[warp * C_ + j]);

    float4 v = make_float4(0.f, 0.f, 0.f, 0.f);
#pragma unroll
    for (int j = 0; j < C_; j++) {
        // row gather: 32 lanes x 16B = 512B contiguous
        float4 e = __ldg(&in4[cidx[j] * (E_ / 4) + lane]);
        v.x += e.x; v.y += e.y; v.z += e.z; v.w += e.w;
    }
    const float inv = 1.0f / (float)C_;
    v.x *= inv; v.y *= inv; v.z *= inv; v.w *= inv;

    // ---- path nodes: partial dots ----
    int pn[D_], cd[D_];
#pragma unroll
    for (int d = 0; d < D_; d++) {
        pn[d] = __ldg(&path[warp * D_ + d]);
        cd[d] = __ldg(&codes[warp * D_ + d]);
    }

    float part[D_];
#pragma unroll
    for (int d = 0; d < D_; d++) {
        float4 u = __ldg(&nd4[pn[d] * (E_ / 4) + lane]);
        part[d] = u.x * v.x + u.y * v.y + u.z * v.z + u.w * v.w;
    }

    // ---- reduce each dot across the warp, accumulate loss ----
    float loss = 0.f;
#pragma unroll
    for (int d = 0; d < D_; d++) {
        float s = part[d];
#pragma unroll
        for (int o = 16; o > 0; o >>= 1)
            s += __shfl_xor_sync(0xFFFFFFFFu, s, o);
        // logit with code sign: p = sigmoid(x) if code==1 else sigmoid(-x)
        float x = cd[d] ? s : -s;
        float sig = __fdividef(1.0f, 1.0f + __expf(-x));
        loss += __logf(sig + EPS_);
    }

    if (lane == 0)
        out[warp] = -loss;
}

extern "C" void kernel_launch(void* const* d_in, const int* in_sizes, int n_in,
                              void* d_out, int out_size)
{
    const int*   ctx      = (const int*)d_in[0];
    const int*   path     = (const int*)d_in[1];
    const int*   codes    = (const int*)d_in[2];
    const float* in_emb   = (const float*)d_in[3];
    const float* node_emb = (const float*)d_in[4];
    float*       out      = (float*)d_out;

    const int threads = 256;               // 8 warps/block
    const int total   = B_ * 32;
    const int blocks  = (total + threads - 1) / threads;
    cbow_hs_kernel<<<blocks, threads>>>(ctx, path, codes, in_emb, node_emb, out);
}